// round 2
// baseline (speedup 1.0000x reference)
#include <cuda_runtime.h>
#include <math.h>

// Problem constants
#define B_SZ 4
#define NSEQ 2048
#define CDIM 1024
#define NHEAD 16
#define HD 64
#define MROWS (B_SZ * NSEQ)        // 8192
#define QKVDIM (3 * CDIM)          // 3072
#define BHTOT (B_SZ * NHEAD)       // 64

// Scratch (static device allocations — allocation-free kernel_launch)
__device__ float g_qkv[MROWS * QKVDIM];          // [8192][3072]
__device__ float g_q[BHTOT * NSEQ * HD];         // [64][2048][64]
__device__ float g_k[BHTOT * NSEQ * HD];
__device__ float g_v[BHTOT * NSEQ * HD];
__device__ float g_att[MROWS * CDIM];            // [8192][1024]

// ---------------------------------------------------------------------------
// SGEMM (NT): C[m,n] = sum_k A[m,k] * B[n,k] (+ bias[n])
// 128x128 block tile, BK=16, 8x8 per-thread tile, 256 threads.
// Assumes M%128==0, N%128==0, K%16==0 (true for all our shapes).
// ---------------------------------------------------------------------------
template <bool BIAS>
__global__ __launch_bounds__(256) void sgemm_nt(
    const float* __restrict__ A, const float* __restrict__ B,
    const float* __restrict__ bias, float* __restrict__ C,
    int M, int N, int K)
{
    __shared__ float As[16][132];
    __shared__ float Bs[16][132];

    const int tid = threadIdx.x;
    const int m0 = blockIdx.y * 128;
    const int n0 = blockIdx.x * 128;
    const int tx = tid & 15;
    const int ty = tid >> 4;

    float acc[8][8];
#pragma unroll
    for (int i = 0; i < 8; i++)
#pragma unroll
        for (int j = 0; j < 8; j++) acc[i][j] = 0.f;

    for (int kt = 0; kt < K; kt += 16) {
#pragma unroll
        for (int i = 0; i < 2; i++) {
            int f = tid + i * 256;          // 0..511
            int row = f >> 2;               // 0..127
            int kc = (f & 3) << 2;          // 0,4,8,12
            float4 av = *reinterpret_cast<const float4*>(
                &A[(size_t)(m0 + row) * K + kt + kc]);
            As[kc + 0][row] = av.x; As[kc + 1][row] = av.y;
            As[kc + 2][row] = av.z; As[kc + 3][row] = av.w;
            float4 bv = *reinterpret_cast<const float4*>(
                &B[(size_t)(n0 + row) * K + kt + kc]);
            Bs[kc + 0][row] = bv.x; Bs[kc + 1][row] = bv.y;
            Bs[kc + 2][row] = bv.z; Bs[kc + 3][row] = bv.w;
        }
        __syncthreads();
#pragma unroll
        for (int k = 0; k < 16; k++) {
            float a[8], b[8];
            float4 a0 = *reinterpret_cast<const float4*>(&As[k][ty * 8]);
            float4 a1 = *reinterpret_cast<const float4*>(&As[k][ty * 8 + 4]);
            a[0] = a0.x; a[1] = a0.y; a[2] = a0.z; a[3] = a0.w;
            a[4] = a1.x; a[5] = a1.y; a[6] = a1.z; a[7] = a1.w;
            float4 b0 = *reinterpret_cast<const float4*>(&Bs[k][tx * 8]);
            float4 b1 = *reinterpret_cast<const float4*>(&Bs[k][tx * 8 + 4]);
            b[0] = b0.x; b[1] = b0.y; b[2] = b0.z; b[3] = b0.w;
            b[4] = b1.x; b[5] = b1.y; b[6] = b1.z; b[7] = b1.w;
#pragma unroll
            for (int i = 0; i < 8; i++)
#pragma unroll
                for (int j = 0; j < 8; j++)
                    acc[i][j] = fmaf(a[i], b[j], acc[i][j]);
        }
        __syncthreads();
    }

    float bv[8];
#pragma unroll
    for (int j = 0; j < 8; j++) bv[j] = BIAS ? bias[n0 + tx * 8 + j] : 0.f;

#pragma unroll
    for (int i = 0; i < 8; i++) {
        size_t m = (size_t)(m0 + ty * 8 + i);
        float4 c0, c1;
        c0.x = acc[i][0] + bv[0]; c0.y = acc[i][1] + bv[1];
        c0.z = acc[i][2] + bv[2]; c0.w = acc[i][3] + bv[3];
        c1.x = acc[i][4] + bv[4]; c1.y = acc[i][5] + bv[5];
        c1.z = acc[i][6] + bv[6]; c1.w = acc[i][7] + bv[7];
        *reinterpret_cast<float4*>(&C[m * N + n0 + tx * 8]) = c0;
        *reinterpret_cast<float4*>(&C[m * N + n0 + tx * 8 + 4]) = c1;
    }
}

// ---------------------------------------------------------------------------
// Prep: split qkv, RMSNorm(q,k), RoPE(q,k), write Q/K/V as [b*H+h][n][64]
// One block (64 threads) per (b,n,h).
// ---------------------------------------------------------------------------
__global__ __launch_bounds__(64) void prep_kernel(
    const float* __restrict__ qkv,
    const float* __restrict__ cosb, const float* __restrict__ sinb,
    const float* __restrict__ qw, const float* __restrict__ kw,
    float* __restrict__ Q, float* __restrict__ K, float* __restrict__ V)
{
    const int bn = blockIdx.x;           // b*2048 + n
    const int h = blockIdx.y;
    const int t = threadIdx.x;           // 0..63
    const int b = bn >> 11;
    const int n = bn & 2047;

    const float* base = qkv + (size_t)bn * QKVDIM;
    float q = base[h * HD + t];
    float k = base[CDIM + h * HD + t];
    float v = base[2 * CDIM + h * HD + t];

    __shared__ float red[128];
    __shared__ float sq[64];
    __shared__ float sk[64];

    red[t] = q * q;
    red[64 + t] = k * k;
    __syncthreads();
#pragma unroll
    for (int s = 32; s > 0; s >>= 1) {
        if (t < s) { red[t] += red[t + s]; red[64 + t] += red[64 + t + s]; }
        __syncthreads();
    }
    float qn = q * rsqrtf(red[0] * (1.f / 64.f) + 1e-6f) * qw[t];
    float kn = k * rsqrtf(red[64] * (1.f / 64.f) + 1e-6f) * kw[t];
    sq[t] = qn;
    sk[t] = kn;
    __syncthreads();
    float qr = (t < 32) ? -sq[t + 32] : sq[t - 32];
    float kr = (t < 32) ? -sk[t + 32] : sk[t - 32];
    float cv = cosb[n * HD + t];
    float sv = sinb[n * HD + t];

    size_t idx = (((size_t)(b * NHEAD + h)) * NSEQ + n) * HD + t;
    Q[idx] = qn * cv + qr * sv;
    K[idx] = kn * cv + kr * sv;
    V[idx] = v;
}

// ---------------------------------------------------------------------------
// Flash attention: one block per (b*H+h, q-tile of 64). 256 threads.
// Shared layouts (stride PAD=68, keeps float4 alignment):
//   QsT[k][r]  (transposed)   KVs: K as [k][c] (transposed), V as [c][d]
//   SsT[c][r]  (transposed)   => all hot LDS are conflict-free float4
// ---------------------------------------------------------------------------
#define PAD 68
#define FA_SMEM (3 * 64 * PAD * 4)

__global__ __launch_bounds__(256) void flash_attn(
    const float* __restrict__ Qg, const float* __restrict__ Kg,
    const float* __restrict__ Vg, float* __restrict__ O)
{
    extern __shared__ float sm[];
    float* QsT = sm;                 // 64*PAD
    float* KVs = sm + 64 * PAD;      // 64*PAD
    float* SsT = sm + 2 * 64 * PAD;  // 64*PAD

    const int bh = blockIdx.x;       // 0..63
    const int qt = blockIdx.y;       // 0..31
    const int b = bh >> 4, h = bh & 15;
    const int t = threadIdx.x;
    const int tx = t & 15;           // column group (cols tx*4..+3)
    const int ty = t >> 4;           // row group   (rows ty*4..+3)

    const float* Qb = Qg + ((size_t)bh * NSEQ + qt * 64) * HD;
    const float* Kb = Kg + (size_t)bh * NSEQ * HD;
    const float* Vb = Vg + (size_t)bh * NSEQ * HD;

    // load Q tile (transposed into QsT[k][r])
#pragma unroll
    for (int i = 0; i < 4; i++) {
        int f = t + i * 256;
        int row = f >> 4;
        int c4 = (f & 15) << 2;
        float4 qv = *reinterpret_cast<const float4*>(&Qb[row * HD + c4]);
        QsT[(c4 + 0) * PAD + row] = qv.x;
        QsT[(c4 + 1) * PAD + row] = qv.y;
        QsT[(c4 + 2) * PAD + row] = qv.z;
        QsT[(c4 + 3) * PAD + row] = qv.w;
    }

    float m[4], l[4];
    float4 o4[4];
#pragma unroll
    for (int i = 0; i < 4; i++) {
        m[i] = -1e30f; l[i] = 0.f;
        o4[i] = make_float4(0.f, 0.f, 0.f, 0.f);
    }

    for (int j = 0; j < NSEQ / 64; j++) {
        __syncthreads();   // prev iter done with KVs/SsT
        // K tile -> KVs transposed [k][c]
#pragma unroll
        for (int i = 0; i < 4; i++) {
            int f = t + i * 256;
            int row = f >> 4;
            int c4 = (f & 15) << 2;
            float4 kv = *reinterpret_cast<const float4*>(
                &Kb[(size_t)(j * 64 + row) * HD + c4]);
            KVs[(c4 + 0) * PAD + row] = kv.x;
            KVs[(c4 + 1) * PAD + row] = kv.y;
            KVs[(c4 + 2) * PAD + row] = kv.z;
            KVs[(c4 + 3) * PAD + row] = kv.w;
        }
        __syncthreads();

        // S = Q K^T (4x4 per thread)
        float s[4][4];
#pragma unroll
        for (int i = 0; i < 4; i++)
#pragma unroll
            for (int jj = 0; jj < 4; jj++) s[i][jj] = 0.f;

#pragma unroll 4
        for (int k = 0; k < HD; k++) {
            float4 qq = *reinterpret_cast<const float4*>(&QsT[k * PAD + ty * 4]);
            float4 kk = *reinterpret_cast<const float4*>(&KVs[k * PAD + tx * 4]);
            float qa[4] = {qq.x, qq.y, qq.z, qq.w};
            float ka[4] = {kk.x, kk.y, kk.z, kk.w};
#pragma unroll
            for (int i = 0; i < 4; i++)
#pragma unroll
                for (int jj = 0; jj < 4; jj++)
                    s[i][jj] = fmaf(qa[i], ka[jj], s[i][jj]);
        }
#pragma unroll
        for (int i = 0; i < 4; i++)
#pragma unroll
            for (int jj = 0; jj < 4; jj++) s[i][jj] *= 0.125f;  // hd^-0.5

        // online softmax
        float mt[4];
#pragma unroll
        for (int i = 0; i < 4; i++)
            mt[i] = fmaxf(fmaxf(s[i][0], s[i][1]), fmaxf(s[i][2], s[i][3]));
#pragma unroll
        for (int off = 1; off < 16; off <<= 1) {
#pragma unroll
            for (int i = 0; i < 4; i++)
                mt[i] = fmaxf(mt[i], __shfl_xor_sync(0xffffffffu, mt[i], off));
        }
        float mn[4], fs[4], ps[4];
#pragma unroll
        for (int i = 0; i < 4; i++) {
            mn[i] = fmaxf(m[i], mt[i]);
            fs[i] = __expf(m[i] - mn[i]);
            m[i] = mn[i];
            ps[i] = 0.f;
        }
#pragma unroll
        for (int jj = 0; jj < 4; jj++) {
            float4 p;
            p.x = __expf(s[0][jj] - mn[0]);
            p.y = __expf(s[1][jj] - mn[1]);
            p.z = __expf(s[2][jj] - mn[2]);
            p.w = __expf(s[3][jj] - mn[3]);
            ps[0] += p.x; ps[1] += p.y; ps[2] += p.z; ps[3] += p.w;
            *reinterpret_cast<float4*>(&SsT[(tx * 4 + jj) * PAD + ty * 4]) = p;
        }
#pragma unroll
        for (int off = 1; off < 16; off <<= 1) {
#pragma unroll
            for (int i = 0; i < 4; i++)
                ps[i] += __shfl_xor_sync(0xffffffffu, ps[i], off);
        }
#pragma unroll
        for (int i = 0; i < 4; i++) {
            l[i] = l[i] * fs[i] + ps[i];
            o4[i].x *= fs[i]; o4[i].y *= fs[i];
            o4[i].z *= fs[i]; o4[i].w *= fs[i];
        }

        __syncthreads();   // done reading K from KVs, SsT fully written
        // V tile -> KVs natural [c][d]
#pragma unroll
        for (int i = 0; i < 4; i++) {
            int f = t + i * 256;
            int row = f >> 4;
            int c4 = (f & 15) << 2;
            *reinterpret_cast<float4*>(&KVs[row * PAD + c4]) =
                *reinterpret_cast<const float4*>(
                    &Vb[(size_t)(j * 64 + row) * HD + c4]);
        }
        __syncthreads();

        // O += P V
#pragma unroll 4
        for (int c = 0; c < 64; c++) {
            float4 pv = *reinterpret_cast<const float4*>(&SsT[c * PAD + ty * 4]);
            float4 vv = *reinterpret_cast<const float4*>(&KVs[c * PAD + tx * 4]);
            o4[0].x = fmaf(pv.x, vv.x, o4[0].x);
            o4[0].y = fmaf(pv.x, vv.y, o4[0].y);
            o4[0].z = fmaf(pv.x, vv.z, o4[0].z);
            o4[0].w = fmaf(pv.x, vv.w, o4[0].w);
            o4[1].x = fmaf(pv.y, vv.x, o4[1].x);
            o4[1].y = fmaf(pv.y, vv.y, o4[1].y);
            o4[1].z = fmaf(pv.y, vv.z, o4[1].z);
            o4[1].w = fmaf(pv.y, vv.w, o4[1].w);
            o4[2].x = fmaf(pv.z, vv.x, o4[2].x);
            o4[2].y = fmaf(pv.z, vv.y, o4[2].y);
            o4[2].z = fmaf(pv.z, vv.z, o4[2].z);
            o4[2].w = fmaf(pv.z, vv.w, o4[2].w);
            o4[3].x = fmaf(pv.w, vv.x, o4[3].x);
            o4[3].y = fmaf(pv.w, vv.y, o4[3].y);
            o4[3].z = fmaf(pv.w, vv.z, o4[3].z);
            o4[3].w = fmaf(pv.w, vv.w, o4[3].w);
        }
    }

    // epilogue: normalize and write [B,N,C] layout for proj GEMM
#pragma unroll
    for (int i = 0; i < 4; i++) {
        float inv = 1.0f / l[i];
        float4 v = o4[i];
        v.x *= inv; v.y *= inv; v.z *= inv; v.w *= inv;
        int row = qt * 64 + ty * 4 + i;
        *reinterpret_cast<float4*>(
            &O[((size_t)b * NSEQ + row) * CDIM + h * HD + tx * 4]) = v;
    }
}

// ---------------------------------------------------------------------------
extern "C" void kernel_launch(void* const* d_in, const int* in_sizes, int n_in,
                              void* d_out, int out_size)
{
    const float* x      = (const float*)d_in[0];
    const float* cosb   = (const float*)d_in[1];
    const float* sinb   = (const float*)d_in[2];
    const float* w_qkv  = (const float*)d_in[3];
    const float* w_proj = (const float*)d_in[4];
    const float* b_proj = (const float*)d_in[5];
    const float* qw     = (const float*)d_in[6];
    const float* kw     = (const float*)d_in[7];
    float* out = (float*)d_out;

    float *qkv, *Qp, *Kp, *Vp, *att;
    cudaGetSymbolAddress((void**)&qkv, g_qkv);
    cudaGetSymbolAddress((void**)&Qp, g_q);
    cudaGetSymbolAddress((void**)&Kp, g_k);
    cudaGetSymbolAddress((void**)&Vp, g_v);
    cudaGetSymbolAddress((void**)&att, g_att);

    // 1) qkv = x @ w_qkv^T
    sgemm_nt<false><<<dim3(QKVDIM / 128, MROWS / 128), 256>>>(
        x, w_qkv, nullptr, qkv, MROWS, QKVDIM, CDIM);

    // 2) split + rmsnorm + rope
    prep_kernel<<<dim3(MROWS, NHEAD), 64>>>(qkv, cosb, sinb, qw, kw, Qp, Kp, Vp);

    // 3) attention
    cudaFuncSetAttribute(flash_attn, cudaFuncAttributeMaxDynamicSharedMemorySize,
                         FA_SMEM);
    flash_attn<<<dim3(BHTOT, NSEQ / 64), 256, FA_SMEM>>>(Qp, Kp, Vp, att);

    // 4) out = att @ w_proj^T + b
    sgemm_nt<true><<<dim3(CDIM / 128, MROWS / 128), 256>>>(
        att, w_proj, b_proj, out, MROWS, CDIM, CDIM);
}

// round 4
// speedup vs baseline: 4.0169x; 4.0169x over previous
#include <cuda_runtime.h>
#include <cuda_bf16.h>
#include <math.h>

// Problem constants
#define B_SZ 4
#define NSEQ 2048
#define CDIM 1024
#define NHEAD 16
#define HD 64
#define MROWS 8192
#define QKVDIM 3072
#define BHTOT 64

// ---------------------------------------------------------------------------
// Static device scratch (allocation-free kernel_launch)
// ---------------------------------------------------------------------------
__device__ float g_qkv[MROWS * QKVDIM];
__device__ __nv_bfloat16 g_ahi[MROWS * CDIM];     // x splits, later att splits
__device__ __nv_bfloat16 g_alo[MROWS * CDIM];
__device__ __nv_bfloat16 g_wqkvhi[QKVDIM * CDIM];
__device__ __nv_bfloat16 g_wqkvlo[QKVDIM * CDIM];
__device__ __nv_bfloat16 g_wprojhi[CDIM * CDIM];
__device__ __nv_bfloat16 g_wprojlo[CDIM * CDIM];
__device__ __nv_bfloat16 g_qhi[BHTOT * NSEQ * HD];
__device__ __nv_bfloat16 g_qlo[BHTOT * NSEQ * HD];
__device__ __nv_bfloat16 g_khi[BHTOT * NSEQ * HD];
__device__ __nv_bfloat16 g_klo[BHTOT * NSEQ * HD];
__device__ __nv_bfloat16 g_vhi[BHTOT * NSEQ * HD];
__device__ __nv_bfloat16 g_vlo[BHTOT * NSEQ * HD];

// ---------------------------------------------------------------------------
// Helpers
// ---------------------------------------------------------------------------
__device__ __forceinline__ unsigned smem_u32(const void* p) {
    unsigned a;
    asm("{ .reg .u64 t; cvta.to.shared.u64 t, %1; cvt.u32.u64 %0, t; }"
        : "=r"(a) : "l"(p));
    return a;
}

__device__ __forceinline__ void ldsm4(unsigned* r, unsigned a) {
    asm volatile("ldmatrix.sync.aligned.m8n8.x4.shared.b16 {%0,%1,%2,%3}, [%4];"
        : "=r"(r[0]), "=r"(r[1]), "=r"(r[2]), "=r"(r[3]) : "r"(a));
}
__device__ __forceinline__ void ldsm4t(unsigned* r, unsigned a) {
    asm volatile("ldmatrix.sync.aligned.m8n8.x4.trans.shared.b16 {%0,%1,%2,%3}, [%4];"
        : "=r"(r[0]), "=r"(r[1]), "=r"(r[2]), "=r"(r[3]) : "r"(a));
}
__device__ __forceinline__ void mma16816(float* d, const unsigned* a,
                                         unsigned b0, unsigned b1) {
    asm volatile(
        "mma.sync.aligned.m16n8k16.row.col.f32.bf16.bf16.f32 "
        "{%0,%1,%2,%3}, {%4,%5,%6,%7}, {%8,%9}, {%0,%1,%2,%3};"
        : "+f"(d[0]), "+f"(d[1]), "+f"(d[2]), "+f"(d[3])
        : "r"(a[0]), "r"(a[1]), "r"(a[2]), "r"(a[3]), "r"(b0), "r"(b1));
}

#define CP16(sa, g) \
    asm volatile("cp.async.cg.shared.global [%0], [%1], 16;" :: "r"(sa), "l"(g))
#define CP_COMMIT() asm volatile("cp.async.commit_group;")
#define CP_WAIT1()  asm volatile("cp.async.wait_group 1;")
#define CP_WAIT0()  asm volatile("cp.async.wait_group 0;")

// chunk swizzle: 128B rows, 8 x 16B chunks
__device__ __forceinline__ unsigned swz(int row, int chunk) {
    return (unsigned)(row * 128 + ((chunk ^ (row & 7)) * 16));
}

// FMA-only exp (no MUFU, no CVT). Valid for x <= 0 (clamped at -80).
__device__ __forceinline__ float fast_exp(float x) {
    x = fmaxf(x, -80.f);
    float t = fmaf(x, 1.442695041f, 12582912.f);
    int ebits = __float_as_int(t) << 23;
    float fi = t - 12582912.f;
    float f = fmaf(x, 1.442695041f, -fi);
    float p = 1.3333558e-3f;
    p = fmaf(p, f, 9.6181291e-3f);
    p = fmaf(p, f, 5.5504109e-2f);
    p = fmaf(p, f, 2.4022651e-1f);
    p = fmaf(p, f, 6.9314718e-1f);
    p = fmaf(p, f, 1.0f);
    return __int_as_float(__float_as_int(p) + ebits);
}

__device__ __forceinline__ unsigned packbf(float x, float y) {
    __nv_bfloat162 h(__float2bfloat16(x), __float2bfloat16(y));
    return *reinterpret_cast<unsigned*>(&h);
}

__device__ __forceinline__ void split_pair(float x, float y,
                                           unsigned& hi, unsigned& lo) {
    __nv_bfloat16 hx = __float2bfloat16(x), hy = __float2bfloat16(y);
    float rx = x - __bfloat162float(hx);
    float ry = y - __bfloat162float(hy);
    __nv_bfloat162 H(hx, hy);
    __nv_bfloat162 L(__float2bfloat16(rx), __float2bfloat16(ry));
    hi = *reinterpret_cast<unsigned*>(&H);
    lo = *reinterpret_cast<unsigned*>(&L);
}

__device__ __forceinline__ void store_hl(__nv_bfloat16* H, __nv_bfloat16* L,
                                         size_t i, float v) {
    __nv_bfloat16 h = __float2bfloat16(v);
    H[i] = h;
    L[i] = __float2bfloat16(v - __bfloat162float(h));
}

// ---------------------------------------------------------------------------
// float -> (bf16 hi, bf16 lo) split
// ---------------------------------------------------------------------------
__global__ __launch_bounds__(256) void split_hi_lo(
    const float* __restrict__ src, __nv_bfloat16* __restrict__ hi,
    __nv_bfloat16* __restrict__ lo, int n4)
{
    int i = blockIdx.x * 256 + threadIdx.x;
    if (i >= n4) return;
    float4 v = reinterpret_cast<const float4*>(src)[i];
    unsigned h01, l01, h23, l23;
    split_pair(v.x, v.y, h01, l01);
    split_pair(v.z, v.w, h23, l23);
    reinterpret_cast<unsigned*>(hi)[2 * i]     = h01;
    reinterpret_cast<unsigned*>(hi)[2 * i + 1] = h23;
    reinterpret_cast<unsigned*>(lo)[2 * i]     = l01;
    reinterpret_cast<unsigned*>(lo)[2 * i + 1] = l23;
}

// ---------------------------------------------------------------------------
// HMMA GEMM (NT): C[m,n] = sum_k A[m,k]*B[n,k] (+bias), hi/lo 3-pass.
// 128x128 tile, BK=64, K=1024 fixed, 256 threads (8 warps, 2x4).
// ---------------------------------------------------------------------------
#define GEMM_SMEM 65536
#define KITERS 16
#define GITERS 48

template <bool BIAS>
__global__ __launch_bounds__(256) void gemm_hmma(
    const __nv_bfloat16* __restrict__ Ahi, const __nv_bfloat16* __restrict__ Alo,
    const __nv_bfloat16* __restrict__ Bhi, const __nv_bfloat16* __restrict__ Blo,
    const float* __restrict__ bias, float* __restrict__ C, int N)
{
    extern __shared__ __align__(128) char smc[];
    const unsigned sb = smem_u32(smc);
    const int t = threadIdx.x, lane = t & 31, wid = t >> 5;
    const int wm = wid & 1, wn = wid >> 1;
    const int m0 = blockIdx.y * 128, n0 = blockIdx.x * 128;
    const int K = 1024;
    const int grp = lane >> 3, ri = lane & 7;

    float acc[4][4][4];
#pragma unroll
    for (int a = 0; a < 4; a++)
#pragma unroll
        for (int b = 0; b < 4; b++)
#pragma unroll
            for (int c = 0; c < 4; c++) acc[a][b][c] = 0.f;

    const int row = t >> 1;
    const int cbase = (t & 1) * 4;

    // stage loader
    auto issue = [&](int it, int s) {
        const int seg = it >> 4;                 // 0,1,2
        const int k0 = (it & 15) * 64;
        const __nv_bfloat16* Ap = (seg == 2) ? Alo : Ahi;
        const __nv_bfloat16* Bp = (seg == 0) ? Bhi : ((seg == 1) ? Blo : Bhi);
        const unsigned ab = sb + s * 32768;
        const unsigned bb = ab + 16384;
#pragma unroll
        for (int i = 0; i < 4; i++) {
            const int ch = cbase + i;
            CP16(ab + swz(row, ch), Ap + (size_t)(m0 + row) * K + k0 + ch * 8);
            CP16(bb + swz(row, ch), Bp + (size_t)(n0 + row) * K + k0 + ch * 8);
        }
    };

    issue(0, 0);
    CP_COMMIT();

    for (int it = 0; it < GITERS; it++) {
        if (it + 1 < GITERS) {
            issue(it + 1, (it + 1) & 1);
            CP_COMMIT();
            CP_WAIT1();
        } else {
            CP_WAIT0();
        }
        __syncthreads();
        const unsigned ab = sb + (it & 1) * 32768;
        const unsigned bb = ab + 16384;
#pragma unroll
        for (int s4 = 0; s4 < 4; s4++) {
            unsigned af[4][4], bfr[2][4];
#pragma unroll
            for (int mt = 0; mt < 4; mt++) {
                int r = wm * 64 + mt * 16 + (grp & 1) * 8 + ri;
                int ch = s4 * 2 + (grp >> 1);
                ldsm4(af[mt], ab + swz(r, ch));
            }
#pragma unroll
            for (int np = 0; np < 2; np++) {
                int r = wn * 32 + np * 16 + ((grp >> 1) & 1) * 8 + ri;
                int ch = s4 * 2 + (grp & 1);
                ldsm4(bfr[np], bb + swz(r, ch));
            }
#pragma unroll
            for (int mt = 0; mt < 4; mt++)
#pragma unroll
                for (int np = 0; np < 2; np++) {
                    mma16816(acc[mt][2 * np], af[mt], bfr[np][0], bfr[np][1]);
                    mma16816(acc[mt][2 * np + 1], af[mt], bfr[np][2], bfr[np][3]);
                }
        }
        __syncthreads();
    }

    // epilogue
#pragma unroll
    for (int mt = 0; mt < 4; mt++)
#pragma unroll
        for (int nt = 0; nt < 4; nt++) {
            int col = n0 + wn * 32 + nt * 8 + (lane & 3) * 2;
            int r0 = m0 + wm * 64 + mt * 16 + (lane >> 2);
            float bx = 0.f, by = 0.f;
            if (BIAS) { bx = bias[col]; by = bias[col + 1]; }
            float2 v0 = make_float2(acc[mt][nt][0] + bx, acc[mt][nt][1] + by);
            float2 v1 = make_float2(acc[mt][nt][2] + bx, acc[mt][nt][3] + by);
            *reinterpret_cast<float2*>(&C[(size_t)r0 * N + col]) = v0;
            *reinterpret_cast<float2*>(&C[(size_t)(r0 + 8) * N + col]) = v1;
        }
}

// ---------------------------------------------------------------------------
// Prep: split qkv, RMSNorm(q,k), RoPE(q,k); emit bf16 hi/lo Q (pre-scaled by
// 1/8), K, V in [b*H+h][n][64] layout. Warp per (b,n,h).
// ---------------------------------------------------------------------------
__global__ __launch_bounds__(256) void prep_kernel(
    const float* __restrict__ qkv,
    const float* __restrict__ cosb, const float* __restrict__ sinb,
    const float* __restrict__ qw, const float* __restrict__ kw,
    __nv_bfloat16* __restrict__ Qh, __nv_bfloat16* __restrict__ Ql,
    __nv_bfloat16* __restrict__ Kh, __nv_bfloat16* __restrict__ Kl,
    __nv_bfloat16* __restrict__ Vh, __nv_bfloat16* __restrict__ Vl)
{
    const int bn = blockIdx.x;
    const int h = (blockIdx.y << 3) | (threadIdx.x >> 5);
    const int l = threadIdx.x & 31;
    const int b = bn >> 11;
    const int n = bn & 2047;

    const float* base = qkv + (size_t)bn * QKVDIM + h * HD;
    float q1 = base[l],            q2 = base[l + 32];
    float k1 = base[CDIM + l],     k2 = base[CDIM + l + 32];
    float v1 = base[2 * CDIM + l], v2 = base[2 * CDIM + l + 32];

    float sq = q1 * q1 + q2 * q2;
    float sk = k1 * k1 + k2 * k2;
#pragma unroll
    for (int o = 16; o > 0; o >>= 1) {
        sq += __shfl_xor_sync(0xffffffffu, sq, o);
        sk += __shfl_xor_sync(0xffffffffu, sk, o);
    }
    float rq = rsqrtf(sq * (1.f / 64.f) + 1e-6f);
    float rk = rsqrtf(sk * (1.f / 64.f) + 1e-6f);
    q1 *= rq * qw[l]; q2 *= rq * qw[l + 32];
    k1 *= rk * kw[l]; k2 *= rk * kw[l + 32];

    float c1 = cosb[n * HD + l], c2 = cosb[n * HD + l + 32];
    float s1 = sinb[n * HD + l], s2 = sinb[n * HD + l + 32];

    size_t o = (((size_t)(b * NHEAD + h)) * NSEQ + n) * HD;
    store_hl(Qh, Ql, o + l,      (q1 * c1 - q2 * s1) * 0.125f);
    store_hl(Qh, Ql, o + l + 32, (q2 * c2 + q1 * s2) * 0.125f);
    store_hl(Kh, Kl, o + l,      k1 * c1 - k2 * s1);
    store_hl(Kh, Kl, o + l + 32, k2 * c2 + k1 * s2);
    store_hl(Vh, Vl, o + l,      v1);
    store_hl(Vh, Vl, o + l + 32, v2);
}

// ---------------------------------------------------------------------------
// Flash attention on HMMA. 128 threads (4 warps, m16 each -> 64 q rows).
// KV tiles of 64, cp.async double-buffered. Emits att as hi/lo bf16.
// SMEM: Qhi 8K | Qlo 8K | stage{Khi,Klo,Vhi,Vlo}x2 = 16K + 64K = 80K
// ---------------------------------------------------------------------------
#define FA_SMEM 81920

__global__ __launch_bounds__(128) void flash_hmma(
    const __nv_bfloat16* __restrict__ Qh, const __nv_bfloat16* __restrict__ Ql,
    const __nv_bfloat16* __restrict__ Kh, const __nv_bfloat16* __restrict__ Kl,
    const __nv_bfloat16* __restrict__ Vh, const __nv_bfloat16* __restrict__ Vl,
    __nv_bfloat16* __restrict__ Ohi, __nv_bfloat16* __restrict__ Olo)
{
    extern __shared__ __align__(128) char smc[];
    const unsigned sb = smem_u32(smc);
    const int t = threadIdx.x, lane = t & 31, w = t >> 5;
    const int bh = blockIdx.x, qt = blockIdx.y;
    const int b = bh >> 4, h = bh & 15;
    const int grp = lane >> 3, ri = lane & 7;

    const size_t qoff = ((size_t)bh * NSEQ + qt * 64) * HD;
    const size_t kvoff = (size_t)bh * NSEQ * HD;

    const int row = t >> 1;
    const int cbase = (t & 1) * 4;

    const __nv_bfloat16* mats[4] = {Kh, Kl, Vh, Vl};

    auto issue = [&](int j, int s) {
        const unsigned stb = sb + 16384 + s * 32768;
#pragma unroll
        for (int m = 0; m < 4; m++) {
            const __nv_bfloat16* g = mats[m] + kvoff + (size_t)(j * 64 + row) * HD;
            const unsigned mb = stb + m * 8192;
#pragma unroll
            for (int i = 0; i < 4; i++) {
                const int ch = cbase + i;
                CP16(mb + swz(row, ch), g + ch * 8);
            }
        }
    };

    issue(0, 0);
    CP_COMMIT();

    // Q tiles -> smem (swizzled), then A-frags into registers
    {
        const __nv_bfloat16* gqh = Qh + qoff + (size_t)row * HD;
        const __nv_bfloat16* gql = Ql + qoff + (size_t)row * HD;
#pragma unroll
        for (int i = 0; i < 4; i++) {
            const int ch = cbase + i;
            *reinterpret_cast<uint4*>(smc + swz(row, ch)) =
                *reinterpret_cast<const uint4*>(gqh + ch * 8);
            *reinterpret_cast<uint4*>(smc + 8192 + swz(row, ch)) =
                *reinterpret_cast<const uint4*>(gql + ch * 8);
        }
    }
    __syncthreads();

    unsigned qh[4][4], ql[4][4];
#pragma unroll
    for (int kt = 0; kt < 4; kt++) {
        int r = w * 16 + (grp & 1) * 8 + ri;
        int ch = kt * 2 + (grp >> 1);
        ldsm4(qh[kt], sb + swz(r, ch));
        ldsm4(ql[kt], sb + 8192 + swz(r, ch));
    }

    float o[8][4];
#pragma unroll
    for (int d = 0; d < 8; d++)
#pragma unroll
        for (int c = 0; c < 4; c++) o[d][c] = 0.f;
    float m0r = -1e30f, m1r = -1e30f, l0r = 0.f, l1r = 0.f;

    for (int j = 0; j < NSEQ / 64; j++) {
        if (j + 1 < NSEQ / 64) {
            issue(j + 1, (j + 1) & 1);
            CP_COMMIT();
            CP_WAIT1();
        } else {
            CP_WAIT0();
        }
        __syncthreads();
        const unsigned stb = sb + 16384 + (j & 1) * 32768;

        // ---- S = Q K^T (3-pass hi/lo) ----
        float s[8][4];
#pragma unroll
        for (int nt = 0; nt < 8; nt++)
#pragma unroll
            for (int c = 0; c < 4; c++) s[nt][c] = 0.f;

#pragma unroll
        for (int kt = 0; kt < 4; kt++) {
#pragma unroll
            for (int np = 0; np < 4; np++) {
                int r = np * 16 + ((grp >> 1) & 1) * 8 + ri;
                int ch = kt * 2 + (grp & 1);
                unsigned kh[4], kl[4];
                ldsm4(kh, stb + swz(r, ch));
                ldsm4(kl, stb + 8192 + swz(r, ch));
                mma16816(s[2 * np],     qh[kt], kh[0], kh[1]);
                mma16816(s[2 * np + 1], qh[kt], kh[2], kh[3]);
                mma16816(s[2 * np],     qh[kt], kl[0], kl[1]);
                mma16816(s[2 * np + 1], qh[kt], kl[2], kl[3]);
                mma16816(s[2 * np],     ql[kt], kh[0], kh[1]);
                mma16816(s[2 * np + 1], ql[kt], kh[2], kh[3]);
            }
        }

        // ---- online softmax (FMA-only exp) ----
        float mt0 = -1e30f, mt1 = -1e30f;
#pragma unroll
        for (int nt = 0; nt < 8; nt++) {
            mt0 = fmaxf(mt0, fmaxf(s[nt][0], s[nt][1]));
            mt1 = fmaxf(mt1, fmaxf(s[nt][2], s[nt][3]));
        }
        mt0 = fmaxf(mt0, __shfl_xor_sync(0xffffffffu, mt0, 1));
        mt0 = fmaxf(mt0, __shfl_xor_sync(0xffffffffu, mt0, 2));
        mt1 = fmaxf(mt1, __shfl_xor_sync(0xffffffffu, mt1, 1));
        mt1 = fmaxf(mt1, __shfl_xor_sync(0xffffffffu, mt1, 2));
        float mn0 = fmaxf(m0r, mt0), mn1 = fmaxf(m1r, mt1);
        float fs0 = fast_exp(m0r - mn0), fs1 = fast_exp(m1r - mn1);
        m0r = mn0; m1r = mn1;
        float ps0 = 0.f, ps1 = 0.f;
#pragma unroll
        for (int nt = 0; nt < 8; nt++) {
            s[nt][0] = fast_exp(s[nt][0] - mn0);
            s[nt][1] = fast_exp(s[nt][1] - mn0);
            s[nt][2] = fast_exp(s[nt][2] - mn1);
            s[nt][3] = fast_exp(s[nt][3] - mn1);
            ps0 += s[nt][0] + s[nt][1];
            ps1 += s[nt][2] + s[nt][3];
        }
        ps0 += __shfl_xor_sync(0xffffffffu, ps0, 1);
        ps0 += __shfl_xor_sync(0xffffffffu, ps0, 2);
        ps1 += __shfl_xor_sync(0xffffffffu, ps1, 1);
        ps1 += __shfl_xor_sync(0xffffffffu, ps1, 2);
        l0r = l0r * fs0 + ps0;
        l1r = l1r * fs1 + ps1;
#pragma unroll
        for (int d = 0; d < 8; d++) {
            o[d][0] *= fs0; o[d][1] *= fs0;
            o[d][2] *= fs1; o[d][3] *= fs1;
        }

        // ---- O += P V (3-pass hi/lo) ----
#pragma unroll
        for (int ct = 0; ct < 4; ct++) {
            unsigned ph[4], pl[4];
            split_pair(s[2 * ct][0],     s[2 * ct][1],     ph[0], pl[0]);
            split_pair(s[2 * ct][2],     s[2 * ct][3],     ph[1], pl[1]);
            split_pair(s[2 * ct + 1][0], s[2 * ct + 1][1], ph[2], pl[2]);
            split_pair(s[2 * ct + 1][2], s[2 * ct + 1][3], ph[3], pl[3]);
#pragma unroll
            for (int dp = 0; dp < 4; dp++) {
                int r = ct * 16 + (lane & 15);
                int ch = dp * 2 + (lane >> 4);
                unsigned vh[4], vl[4];
                ldsm4t(vh, stb + 16384 + swz(r, ch));
                ldsm4t(vl, stb + 24576 + swz(r, ch));
                mma16816(o[2 * dp],     ph, vh[0], vh[1]);
                mma16816(o[2 * dp + 1], ph, vh[2], vh[3]);
                mma16816(o[2 * dp],     ph, vl[0], vl[1]);
                mma16816(o[2 * dp + 1], ph, vl[2], vl[3]);
                mma16816(o[2 * dp],     pl, vh[0], vh[1]);
                mma16816(o[2 * dp + 1], pl, vh[2], vh[3]);
            }
        }
        __syncthreads();
    }

    // ---- epilogue: O/l -> hi/lo bf16 att in [B,N,C] layout ----
    const float inv0 = 1.0f / l0r, inv1 = 1.0f / l1r;
#pragma unroll
    for (int dt = 0; dt < 8; dt++) {
        int col = h * 64 + dt * 8 + (lane & 3) * 2;
        int r0 = qt * 64 + w * 16 + (lane >> 2);
        size_t i0 = ((size_t)b * NSEQ + r0) * CDIM + col;
        size_t i1 = ((size_t)b * NSEQ + r0 + 8) * CDIM + col;
        unsigned h0, l0, h1, l1;
        split_pair(o[dt][0] * inv0, o[dt][1] * inv0, h0, l0);
        split_pair(o[dt][2] * inv1, o[dt][3] * inv1, h1, l1);
        *reinterpret_cast<unsigned*>(&Ohi[i0]) = h0;
        *reinterpret_cast<unsigned*>(&Olo[i0]) = l0;
        *reinterpret_cast<unsigned*>(&Ohi[i1]) = h1;
        *reinterpret_cast<unsigned*>(&Olo[i1]) = l1;
    }
}

// ---------------------------------------------------------------------------
extern "C" void kernel_launch(void* const* d_in, const int* in_sizes, int n_in,
                              void* d_out, int out_size)
{
    const float* x      = (const float*)d_in[0];
    const float* cosb   = (const float*)d_in[1];
    const float* sinb   = (const float*)d_in[2];
    const float* w_qkv  = (const float*)d_in[3];
    const float* w_proj = (const float*)d_in[4];
    const float* b_proj = (const float*)d_in[5];
    const float* qw     = (const float*)d_in[6];
    const float* kw     = (const float*)d_in[7];
    float* out = (float*)d_out;

    float* qkv;
    __nv_bfloat16 *ahi, *alo, *wqh, *wql, *wph, *wpl;
    __nv_bfloat16 *qhi, *qlo, *khi, *klo, *vhi, *vlo;
    cudaGetSymbolAddress((void**)&qkv, g_qkv);
    cudaGetSymbolAddress((void**)&ahi, g_ahi);
    cudaGetSymbolAddress((void**)&alo, g_alo);
    cudaGetSymbolAddress((void**)&wqh, g_wqkvhi);
    cudaGetSymbolAddress((void**)&wql, g_wqkvlo);
    cudaGetSymbolAddress((void**)&wph, g_wprojhi);
    cudaGetSymbolAddress((void**)&wpl, g_wprojlo);
    cudaGetSymbolAddress((void**)&qhi, g_qhi);
    cudaGetSymbolAddress((void**)&qlo, g_qlo);
    cudaGetSymbolAddress((void**)&khi, g_khi);
    cudaGetSymbolAddress((void**)&klo, g_klo);
    cudaGetSymbolAddress((void**)&vhi, g_vhi);
    cudaGetSymbolAddress((void**)&vlo, g_vlo);

    cudaFuncSetAttribute(gemm_hmma<false>,
                         cudaFuncAttributeMaxDynamicSharedMemorySize, GEMM_SMEM);
    cudaFuncSetAttribute(gemm_hmma<true>,
                         cudaFuncAttributeMaxDynamicSharedMemorySize, GEMM_SMEM);
    cudaFuncSetAttribute(flash_hmma,
                         cudaFuncAttributeMaxDynamicSharedMemorySize, FA_SMEM);

    // 0) hi/lo splits of x and both weights
    split_hi_lo<<<MROWS * CDIM / 4 / 256, 256>>>(x, ahi, alo, MROWS * CDIM / 4);
    split_hi_lo<<<QKVDIM * CDIM / 4 / 256, 256>>>(w_qkv, wqh, wql, QKVDIM * CDIM / 4);
    split_hi_lo<<<CDIM * CDIM / 4 / 256, 256>>>(w_proj, wph, wpl, CDIM * CDIM / 4);

    // 1) qkv = x @ w_qkv^T
    gemm_hmma<false><<<dim3(QKVDIM / 128, MROWS / 128), 256, GEMM_SMEM>>>(
        ahi, alo, wqh, wql, nullptr, qkv, QKVDIM);

    // 2) rmsnorm + rope -> hi/lo Q(pre-scaled), K, V
    prep_kernel<<<dim3(MROWS, 2), 256>>>(qkv, cosb, sinb, qw, kw,
                                         qhi, qlo, khi, klo, vhi, vlo);

    // 3) flash attention -> att hi/lo (into g_ahi/g_alo)
    flash_hmma<<<dim3(BHTOT, NSEQ / 64), 128, FA_SMEM>>>(
        qhi, qlo, khi, klo, vhi, vlo, ahi, alo);

    // 4) out = att @ w_proj^T + b
    gemm_hmma<true><<<dim3(CDIM / 128, MROWS / 128), 256, GEMM_SMEM>>>(
        ahi, alo, wph, wpl, b_proj, out, CDIM);
}

// round 5
// speedup vs baseline: 5.4259x; 1.3508x over previous
#include <cuda_runtime.h>
#include <cuda_bf16.h>
#include <math.h>

// Problem constants
#define B_SZ 4
#define NSEQ 2048
#define CDIM 1024
#define NHEAD 16
#define HD 64
#define MROWS 8192
#define QKVDIM 3072
#define BHTOT 64

// ---------------------------------------------------------------------------
// Static device scratch (allocation-free kernel_launch)
// ---------------------------------------------------------------------------
__device__ float g_qkv[MROWS * QKVDIM];
__device__ __nv_bfloat16 g_ahi[MROWS * CDIM];     // x splits, later att splits
__device__ __nv_bfloat16 g_alo[MROWS * CDIM];
__device__ __nv_bfloat16 g_wqkvhi[QKVDIM * CDIM];
__device__ __nv_bfloat16 g_wqkvlo[QKVDIM * CDIM];
__device__ __nv_bfloat16 g_wprojhi[CDIM * CDIM];
__device__ __nv_bfloat16 g_wprojlo[CDIM * CDIM];
__device__ __nv_bfloat16 g_qhi[BHTOT * NSEQ * HD];
__device__ __nv_bfloat16 g_qlo[BHTOT * NSEQ * HD];
__device__ __nv_bfloat16 g_khi[BHTOT * NSEQ * HD];
__device__ __nv_bfloat16 g_klo[BHTOT * NSEQ * HD];
__device__ __nv_bfloat16 g_vhi[BHTOT * NSEQ * HD];
__device__ __nv_bfloat16 g_vlo[BHTOT * NSEQ * HD];

// ---------------------------------------------------------------------------
// Helpers
// ---------------------------------------------------------------------------
__device__ __forceinline__ unsigned smem_u32(const void* p) {
    unsigned a;
    asm("{ .reg .u64 t; cvta.to.shared.u64 t, %1; cvt.u32.u64 %0, t; }"
        : "=r"(a) : "l"(p));
    return a;
}

__device__ __forceinline__ void ldsm4(unsigned* r, unsigned a) {
    asm volatile("ldmatrix.sync.aligned.m8n8.x4.shared.b16 {%0,%1,%2,%3}, [%4];"
        : "=r"(r[0]), "=r"(r[1]), "=r"(r[2]), "=r"(r[3]) : "r"(a));
}
__device__ __forceinline__ void ldsm4t(unsigned* r, unsigned a) {
    asm volatile("ldmatrix.sync.aligned.m8n8.x4.trans.shared.b16 {%0,%1,%2,%3}, [%4];"
        : "=r"(r[0]), "=r"(r[1]), "=r"(r[2]), "=r"(r[3]) : "r"(a));
}
__device__ __forceinline__ void mma16816(float* d, const unsigned* a,
                                         unsigned b0, unsigned b1) {
    asm volatile(
        "mma.sync.aligned.m16n8k16.row.col.f32.bf16.bf16.f32 "
        "{%0,%1,%2,%3}, {%4,%5,%6,%7}, {%8,%9}, {%0,%1,%2,%3};"
        : "+f"(d[0]), "+f"(d[1]), "+f"(d[2]), "+f"(d[3])
        : "r"(a[0]), "r"(a[1]), "r"(a[2]), "r"(a[3]), "r"(b0), "r"(b1));
}

#define CP16(sa, g) \
    asm volatile("cp.async.cg.shared.global [%0], [%1], 16;" :: "r"(sa), "l"(g))
#define CP_COMMIT() asm volatile("cp.async.commit_group;")
#define CP_WAIT1()  asm volatile("cp.async.wait_group 1;")
#define CP_WAIT0()  asm volatile("cp.async.wait_group 0;")

// chunk swizzle: 128B rows, 8 x 16B chunks
__device__ __forceinline__ unsigned swz(int row, int chunk) {
    return (unsigned)(row * 128 + ((chunk ^ (row & 7)) * 16));
}

// FMA-only exp (no MUFU, no CVT). Valid for |x| <= ~80 (clamped below).
__device__ __forceinline__ float fast_exp(float x) {
    x = fmaxf(x, -80.f);
    float t = fmaf(x, 1.442695041f, 12582912.f);
    int ebits = __float_as_int(t) << 23;
    float fi = t - 12582912.f;
    float f = fmaf(x, 1.442695041f, -fi);
    float p = 1.3333558e-3f;
    p = fmaf(p, f, 9.6181291e-3f);
    p = fmaf(p, f, 5.5504109e-2f);
    p = fmaf(p, f, 2.4022651e-1f);
    p = fmaf(p, f, 6.9314718e-1f);
    p = fmaf(p, f, 1.0f);
    return __int_as_float(__float_as_int(p) + ebits);
}

__device__ __forceinline__ void split_pair(float x, float y,
                                           unsigned& hi, unsigned& lo) {
    __nv_bfloat16 hx = __float2bfloat16(x), hy = __float2bfloat16(y);
    float rx = x - __bfloat162float(hx);
    float ry = y - __bfloat162float(hy);
    __nv_bfloat162 H(hx, hy);
    __nv_bfloat162 L(__float2bfloat16(rx), __float2bfloat16(ry));
    hi = *reinterpret_cast<unsigned*>(&H);
    lo = *reinterpret_cast<unsigned*>(&L);
}

__device__ __forceinline__ void store_hl(__nv_bfloat16* H, __nv_bfloat16* L,
                                         size_t i, float v) {
    __nv_bfloat16 h = __float2bfloat16(v);
    H[i] = h;
    L[i] = __float2bfloat16(v - __bfloat162float(h));
}

// ---------------------------------------------------------------------------
// float -> (bf16 hi, bf16 lo) split
// ---------------------------------------------------------------------------
__global__ __launch_bounds__(256) void split_hi_lo(
    const float* __restrict__ src, __nv_bfloat16* __restrict__ hi,
    __nv_bfloat16* __restrict__ lo, int n4)
{
    int i = blockIdx.x * 256 + threadIdx.x;
    if (i >= n4) return;
    float4 v = reinterpret_cast<const float4*>(src)[i];
    unsigned h01, l01, h23, l23;
    split_pair(v.x, v.y, h01, l01);
    split_pair(v.z, v.w, h23, l23);
    reinterpret_cast<unsigned*>(hi)[2 * i]     = h01;
    reinterpret_cast<unsigned*>(hi)[2 * i + 1] = h23;
    reinterpret_cast<unsigned*>(lo)[2 * i]     = l01;
    reinterpret_cast<unsigned*>(lo)[2 * i + 1] = l23;
}

// ---------------------------------------------------------------------------
// HMMA GEMM (NT): C[m,n] = sum_k A[m,k]*B[n,k] (+bias), hi/lo 3-pass fused.
// 128x128 tile, BK=64 stage holds {Ahi,Alo,Bhi,Blo}; 3 passes per stage.
// 3-stage cp.async pipeline, one __syncthreads per stage. 256 threads.
// ---------------------------------------------------------------------------
#define GS_STAGE 65536
#define GEMM_SMEM (3 * GS_STAGE)     // 196608
#define NSTAGES 16                   // K=1024 / 64

template <bool BIAS>
__global__ __launch_bounds__(256, 1) void gemm_hmma(
    const __nv_bfloat16* __restrict__ Ahi, const __nv_bfloat16* __restrict__ Alo,
    const __nv_bfloat16* __restrict__ Bhi, const __nv_bfloat16* __restrict__ Blo,
    const float* __restrict__ bias, float* __restrict__ C, int N)
{
    extern __shared__ __align__(128) char smc[];
    const unsigned sb = smem_u32(smc);
    const int t = threadIdx.x, lane = t & 31, wid = t >> 5;
    const int wm = wid & 1, wn = wid >> 1;
    const int m0 = blockIdx.y * 128, n0 = blockIdx.x * 128;
    const int K = 1024;
    const int grp = lane >> 3, ri = lane & 7;

    float acc[4][4][4];
#pragma unroll
    for (int a = 0; a < 4; a++)
#pragma unroll
        for (int b = 0; b < 4; b++)
#pragma unroll
            for (int c = 0; c < 4; c++) acc[a][b][c] = 0.f;

    const __nv_bfloat16* srcs[4] = {
        Ahi + (size_t)m0 * K, Alo + (size_t)m0 * K,
        Bhi + (size_t)n0 * K, Blo + (size_t)n0 * K };

    // stage loader: 64KB = 4 mats x 128 rows x 8 chunks; 16 chunks/thread
    auto issue = [&](int s, int buf) {
        const int k0 = s * 64;
        const unsigned stb = sb + buf * GS_STAGE;
#pragma unroll
        for (int m = 0; m < 4; m++) {
            const unsigned mb = stb + m * 16384;
            const __nv_bfloat16* g = srcs[m] + k0;
#pragma unroll
            for (int i = 0; i < 4; i++) {
                int idx = i * 256 + t;
                int r = idx >> 3, ch = idx & 7;
                CP16(mb + swz(r, ch), g + (size_t)r * K + ch * 8);
            }
        }
    };

    issue(0, 0); CP_COMMIT();
    issue(1, 1); CP_COMMIT();

    for (int it = 0; it < NSTAGES; it++) {
        if (it == NSTAGES - 1) { CP_WAIT0(); } else { CP_WAIT1(); }
        __syncthreads();
        if (it + 2 < NSTAGES) {
            int s = it + 2;
            issue(s, s % 3);
            CP_COMMIT();
        }
        const unsigned stb = sb + (it % 3) * GS_STAGE;
        const unsigned abh = stb, abl = stb + 16384;
        const unsigned bbh = stb + 32768, bbl = stb + 49152;
#pragma unroll
        for (int k4 = 0; k4 < 4; k4++) {
            unsigned ah[4][4], al[4][4], bh[2][4], bl[2][4];
#pragma unroll
            for (int mt = 0; mt < 4; mt++) {
                int r = wm * 64 + mt * 16 + (grp & 1) * 8 + ri;
                int ch = k4 * 2 + (grp >> 1);
                ldsm4(ah[mt], abh + swz(r, ch));
                ldsm4(al[mt], abl + swz(r, ch));
            }
#pragma unroll
            for (int np = 0; np < 2; np++) {
                int r = wn * 32 + np * 16 + ((grp >> 1) & 1) * 8 + ri;
                int ch = k4 * 2 + (grp & 1);
                ldsm4(bh[np], bbh + swz(r, ch));
                ldsm4(bl[np], bbl + swz(r, ch));
            }
            // pass 1: Ahi * Bhi
#pragma unroll
            for (int mt = 0; mt < 4; mt++)
#pragma unroll
                for (int np = 0; np < 2; np++) {
                    mma16816(acc[mt][2 * np],     ah[mt], bh[np][0], bh[np][1]);
                    mma16816(acc[mt][2 * np + 1], ah[mt], bh[np][2], bh[np][3]);
                }
            // pass 2: Ahi * Blo
#pragma unroll
            for (int mt = 0; mt < 4; mt++)
#pragma unroll
                for (int np = 0; np < 2; np++) {
                    mma16816(acc[mt][2 * np],     ah[mt], bl[np][0], bl[np][1]);
                    mma16816(acc[mt][2 * np + 1], ah[mt], bl[np][2], bl[np][3]);
                }
            // pass 3: Alo * Bhi
#pragma unroll
            for (int mt = 0; mt < 4; mt++)
#pragma unroll
                for (int np = 0; np < 2; np++) {
                    mma16816(acc[mt][2 * np],     al[mt], bh[np][0], bh[np][1]);
                    mma16816(acc[mt][2 * np + 1], al[mt], bh[np][2], bh[np][3]);
                }
        }
    }

    // epilogue
#pragma unroll
    for (int mt = 0; mt < 4; mt++)
#pragma unroll
        for (int nt = 0; nt < 4; nt++) {
            int col = n0 + wn * 32 + nt * 8 + (lane & 3) * 2;
            int r0 = m0 + wm * 64 + mt * 16 + (lane >> 2);
            float bx = 0.f, by = 0.f;
            if (BIAS) { bx = bias[col]; by = bias[col + 1]; }
            float2 v0 = make_float2(acc[mt][nt][0] + bx, acc[mt][nt][1] + by);
            float2 v1 = make_float2(acc[mt][nt][2] + bx, acc[mt][nt][3] + by);
            *reinterpret_cast<float2*>(&C[(size_t)r0 * N + col]) = v0;
            *reinterpret_cast<float2*>(&C[(size_t)(r0 + 8) * N + col]) = v1;
        }
}

// ---------------------------------------------------------------------------
// Prep: split qkv, RMSNorm(q,k), RoPE(q,k); emit bf16 hi/lo Q (pre-scaled by
// 1/8), K, V in [b*H+h][n][64] layout. Warp per (b,n,h).
// ---------------------------------------------------------------------------
__global__ __launch_bounds__(256) void prep_kernel(
    const float* __restrict__ qkv,
    const float* __restrict__ cosb, const float* __restrict__ sinb,
    const float* __restrict__ qw, const float* __restrict__ kw,
    __nv_bfloat16* __restrict__ Qh, __nv_bfloat16* __restrict__ Ql,
    __nv_bfloat16* __restrict__ Kh, __nv_bfloat16* __restrict__ Kl,
    __nv_bfloat16* __restrict__ Vh, __nv_bfloat16* __restrict__ Vl)
{
    const int bn = blockIdx.x;
    const int h = (blockIdx.y << 3) | (threadIdx.x >> 5);
    const int l = threadIdx.x & 31;
    const int b = bn >> 11;
    const int n = bn & 2047;

    const float* base = qkv + (size_t)bn * QKVDIM + h * HD;
    float q1 = base[l],            q2 = base[l + 32];
    float k1 = base[CDIM + l],     k2 = base[CDIM + l + 32];
    float v1 = base[2 * CDIM + l], v2 = base[2 * CDIM + l + 32];

    float sq = q1 * q1 + q2 * q2;
    float sk = k1 * k1 + k2 * k2;
#pragma unroll
    for (int o = 16; o > 0; o >>= 1) {
        sq += __shfl_xor_sync(0xffffffffu, sq, o);
        sk += __shfl_xor_sync(0xffffffffu, sk, o);
    }
    float rq = rsqrtf(sq * (1.f / 64.f) + 1e-6f);
    float rk = rsqrtf(sk * (1.f / 64.f) + 1e-6f);
    q1 *= rq * qw[l]; q2 *= rq * qw[l + 32];
    k1 *= rk * kw[l]; k2 *= rk * kw[l + 32];

    float c1 = cosb[n * HD + l], c2 = cosb[n * HD + l + 32];
    float s1 = sinb[n * HD + l], s2 = sinb[n * HD + l + 32];

    size_t o = (((size_t)(b * NHEAD + h)) * NSEQ + n) * HD;
    store_hl(Qh, Ql, o + l,      (q1 * c1 - q2 * s1) * 0.125f);
    store_hl(Qh, Ql, o + l + 32, (q2 * c2 + q1 * s2) * 0.125f);
    store_hl(Kh, Kl, o + l,      k1 * c1 - k2 * s1);
    store_hl(Kh, Kl, o + l + 32, k2 * c2 + k1 * s2);
    store_hl(Vh, Vl, o + l,      v1);
    store_hl(Vh, Vl, o + l + 32, v2);
}

// ---------------------------------------------------------------------------
// Flash attention on HMMA. 256 threads (8 warps, m16 each -> 128 q rows).
// KV tiles of 64, cp.async double-buffered. NO online max: RMS-normed q,k
// with RoPE give |s| <= 32, exp/sums stay well inside fp32 range.
// SMEM: Qhi 16K | Qlo 16K | stage{Khi,Klo,Vhi,Vlo}x2 = 32K + 64K = 96K
// ---------------------------------------------------------------------------
#define FA_SMEM 98304

__global__ __launch_bounds__(256, 2) void flash_hmma(
    const __nv_bfloat16* __restrict__ Qh, const __nv_bfloat16* __restrict__ Ql,
    const __nv_bfloat16* __restrict__ Kh, const __nv_bfloat16* __restrict__ Kl,
    const __nv_bfloat16* __restrict__ Vh, const __nv_bfloat16* __restrict__ Vl,
    __nv_bfloat16* __restrict__ Ohi, __nv_bfloat16* __restrict__ Olo)
{
    extern __shared__ __align__(128) char smc[];
    const unsigned sb = smem_u32(smc);
    const int t = threadIdx.x, lane = t & 31, w = t >> 5;
    const int bh = blockIdx.x, qt = blockIdx.y;
    const int b = bh >> 4, h = bh & 15;
    const int grp = lane >> 3, ri = lane & 7;

    const size_t qoff = ((size_t)bh * NSEQ + qt * 128) * HD;
    const size_t kvoff = (size_t)bh * NSEQ * HD;

    const __nv_bfloat16* mats[4] = {Kh, Kl, Vh, Vl};

    auto issue = [&](int j, int s) {
        const unsigned stb = sb + 32768 + s * 32768;
#pragma unroll
        for (int m = 0; m < 4; m++) {
            const __nv_bfloat16* g = mats[m] + kvoff + (size_t)(j * 64) * HD;
            const unsigned mb = stb + m * 8192;
#pragma unroll
            for (int i = 0; i < 2; i++) {
                int idx = i * 256 + t;
                int r = idx >> 3, ch = idx & 7;
                CP16(mb + swz(r, ch), g + (size_t)r * HD + ch * 8);
            }
        }
    };

    issue(0, 0);
    CP_COMMIT();

    // Q tiles -> smem (swizzled)
    {
#pragma unroll
        for (int i = 0; i < 4; i++) {
            int idx = i * 256 + t;
            int r = idx >> 3, ch = idx & 7;
            *reinterpret_cast<uint4*>(smc + swz(r, ch)) =
                *reinterpret_cast<const uint4*>(Qh + qoff + (size_t)r * HD + ch * 8);
            *reinterpret_cast<uint4*>(smc + 16384 + swz(r, ch)) =
                *reinterpret_cast<const uint4*>(Ql + qoff + (size_t)r * HD + ch * 8);
        }
    }
    __syncthreads();

    unsigned qh[4][4], ql[4][4];
#pragma unroll
    for (int kt = 0; kt < 4; kt++) {
        int r = w * 16 + (grp & 1) * 8 + ri;
        int ch = kt * 2 + (grp >> 1);
        ldsm4(qh[kt], sb + swz(r, ch));
        ldsm4(ql[kt], sb + 16384 + swz(r, ch));
    }

    float o[8][4];
#pragma unroll
    for (int d = 0; d < 8; d++)
#pragma unroll
        for (int c = 0; c < 4; c++) o[d][c] = 0.f;
    float l0r = 0.f, l1r = 0.f;

    for (int j = 0; j < NSEQ / 64; j++) {
        if (j + 1 < NSEQ / 64) {
            issue(j + 1, (j + 1) & 1);
            CP_COMMIT();
            CP_WAIT1();
        } else {
            CP_WAIT0();
        }
        __syncthreads();
        const unsigned stb = sb + 32768 + (j & 1) * 32768;

        // ---- S = Q K^T (3-pass hi/lo) ----
        float s[8][4];
#pragma unroll
        for (int nt = 0; nt < 8; nt++)
#pragma unroll
            for (int c = 0; c < 4; c++) s[nt][c] = 0.f;

#pragma unroll
        for (int kt = 0; kt < 4; kt++) {
#pragma unroll
            for (int np = 0; np < 4; np++) {
                int r = np * 16 + ((grp >> 1) & 1) * 8 + ri;
                int ch = kt * 2 + (grp & 1);
                unsigned kh[4], kl[4];
                ldsm4(kh, stb + swz(r, ch));
                ldsm4(kl, stb + 8192 + swz(r, ch));
                mma16816(s[2 * np],     qh[kt], kh[0], kh[1]);
                mma16816(s[2 * np + 1], qh[kt], kh[2], kh[3]);
                mma16816(s[2 * np],     qh[kt], kl[0], kl[1]);
                mma16816(s[2 * np + 1], qh[kt], kl[2], kl[3]);
                mma16816(s[2 * np],     ql[kt], kh[0], kh[1]);
                mma16816(s[2 * np + 1], ql[kt], kh[2], kh[3]);
            }
        }

        // ---- softmax numerators (no max subtraction needed) ----
        float ps0 = 0.f, ps1 = 0.f;
#pragma unroll
        for (int nt = 0; nt < 8; nt++) {
            s[nt][0] = fast_exp(s[nt][0]);
            s[nt][1] = fast_exp(s[nt][1]);
            s[nt][2] = fast_exp(s[nt][2]);
            s[nt][3] = fast_exp(s[nt][3]);
            ps0 += s[nt][0] + s[nt][1];
            ps1 += s[nt][2] + s[nt][3];
        }
        ps0 += __shfl_xor_sync(0xffffffffu, ps0, 1);
        ps0 += __shfl_xor_sync(0xffffffffu, ps0, 2);
        ps1 += __shfl_xor_sync(0xffffffffu, ps1, 1);
        ps1 += __shfl_xor_sync(0xffffffffu, ps1, 2);
        l0r += ps0;
        l1r += ps1;

        // ---- O += P V (3-pass hi/lo) ----
#pragma unroll
        for (int ct = 0; ct < 4; ct++) {
            unsigned ph[4], pl[4];
            split_pair(s[2 * ct][0],     s[2 * ct][1],     ph[0], pl[0]);
            split_pair(s[2 * ct][2],     s[2 * ct][3],     ph[1], pl[1]);
            split_pair(s[2 * ct + 1][0], s[2 * ct + 1][1], ph[2], pl[2]);
            split_pair(s[2 * ct + 1][2], s[2 * ct + 1][3], ph[3], pl[3]);
#pragma unroll
            for (int dp = 0; dp < 4; dp++) {
                int r = ct * 16 + (lane & 15);
                int ch = dp * 2 + (lane >> 4);
                unsigned vh[4], vl[4];
                ldsm4t(vh, stb + 16384 + swz(r, ch));
                ldsm4t(vl, stb + 24576 + swz(r, ch));
                mma16816(o[2 * dp],     ph, vh[0], vh[1]);
                mma16816(o[2 * dp + 1], ph, vh[2], vh[3]);
                mma16816(o[2 * dp],     ph, vl[0], vl[1]);
                mma16816(o[2 * dp + 1], ph, vl[2], vl[3]);
                mma16816(o[2 * dp],     pl, vh[0], vh[1]);
                mma16816(o[2 * dp + 1], pl, vh[2], vh[3]);
            }
        }
        __syncthreads();
    }

    // ---- epilogue: O/l -> hi/lo bf16 att in [B,N,C] layout ----
    const float inv0 = 1.0f / l0r, inv1 = 1.0f / l1r;
#pragma unroll
    for (int dt = 0; dt < 8; dt++) {
        int col = h * 64 + dt * 8 + (lane & 3) * 2;
        int r0 = qt * 128 + w * 16 + (lane >> 2);
        size_t i0 = ((size_t)b * NSEQ + r0) * CDIM + col;
        size_t i1 = ((size_t)b * NSEQ + r0 + 8) * CDIM + col;
        unsigned h0, l0, h1, l1;
        split_pair(o[dt][0] * inv0, o[dt][1] * inv0, h0, l0);
        split_pair(o[dt][2] * inv1, o[dt][3] * inv1, h1, l1);
        *reinterpret_cast<unsigned*>(&Ohi[i0]) = h0;
        *reinterpret_cast<unsigned*>(&Olo[i0]) = l0;
        *reinterpret_cast<unsigned*>(&Ohi[i1]) = h1;
        *reinterpret_cast<unsigned*>(&Olo[i1]) = l1;
    }
}

// ---------------------------------------------------------------------------
extern "C" void kernel_launch(void* const* d_in, const int* in_sizes, int n_in,
                              void* d_out, int out_size)
{
    const float* x      = (const float*)d_in[0];
    const float* cosb   = (const float*)d_in[1];
    const float* sinb   = (const float*)d_in[2];
    const float* w_qkv  = (const float*)d_in[3];
    const float* w_proj = (const float*)d_in[4];
    const float* b_proj = (const float*)d_in[5];
    const float* qw     = (const float*)d_in[6];
    const float* kw     = (const float*)d_in[7];
    float* out = (float*)d_out;

    float* qkv;
    __nv_bfloat16 *ahi, *alo, *wqh, *wql, *wph, *wpl;
    __nv_bfloat16 *qhi, *qlo, *khi, *klo, *vhi, *vlo;
    cudaGetSymbolAddress((void**)&qkv, g_qkv);
    cudaGetSymbolAddress((void**)&ahi, g_ahi);
    cudaGetSymbolAddress((void**)&alo, g_alo);
    cudaGetSymbolAddress((void**)&wqh, g_wqkvhi);
    cudaGetSymbolAddress((void**)&wql, g_wqkvlo);
    cudaGetSymbolAddress((void**)&wph, g_wprojhi);
    cudaGetSymbolAddress((void**)&wpl, g_wprojlo);
    cudaGetSymbolAddress((void**)&qhi, g_qhi);
    cudaGetSymbolAddress((void**)&qlo, g_qlo);
    cudaGetSymbolAddress((void**)&khi, g_khi);
    cudaGetSymbolAddress((void**)&klo, g_klo);
    cudaGetSymbolAddress((void**)&vhi, g_vhi);
    cudaGetSymbolAddress((void**)&vlo, g_vlo);

    cudaFuncSetAttribute(gemm_hmma<false>,
                         cudaFuncAttributeMaxDynamicSharedMemorySize, GEMM_SMEM);
    cudaFuncSetAttribute(gemm_hmma<true>,
                         cudaFuncAttributeMaxDynamicSharedMemorySize, GEMM_SMEM);
    cudaFuncSetAttribute(flash_hmma,
                         cudaFuncAttributeMaxDynamicSharedMemorySize, FA_SMEM);

    // 0) hi/lo splits of x and both weights
    split_hi_lo<<<MROWS * CDIM / 4 / 256, 256>>>(x, ahi, alo, MROWS * CDIM / 4);
    split_hi_lo<<<QKVDIM * CDIM / 4 / 256, 256>>>(w_qkv, wqh, wql, QKVDIM * CDIM / 4);
    split_hi_lo<<<CDIM * CDIM / 4 / 256, 256>>>(w_proj, wph, wpl, CDIM * CDIM / 4);

    // 1) qkv = x @ w_qkv^T
    gemm_hmma<false><<<dim3(QKVDIM / 128, MROWS / 128), 256, GEMM_SMEM>>>(
        ahi, alo, wqh, wql, nullptr, qkv, QKVDIM);

    // 2) rmsnorm + rope -> hi/lo Q(pre-scaled), K, V
    prep_kernel<<<dim3(MROWS, 2), 256>>>(qkv, cosb, sinb, qw, kw,
                                         qhi, qlo, khi, klo, vhi, vlo);

    // 3) flash attention -> att hi/lo (into g_ahi/g_alo)
    flash_hmma<<<dim3(BHTOT, NSEQ / 128), 256, FA_SMEM>>>(
        qhi, qlo, khi, klo, vhi, vlo, ahi, alo);

    // 4) out = att @ w_proj^T + b
    gemm_hmma<true><<<dim3(CDIM / 128, MROWS / 128), 256, GEMM_SMEM>>>(
        ahi, alo, wph, wpl, b_proj, out, CDIM);
}